// round 12
// baseline (speedup 1.0000x reference)
#include <cuda_runtime.h>

typedef unsigned long long ull;
typedef unsigned int u32;

// ---- f32x2 packed helpers (Blackwell) ----
__device__ __forceinline__ ull ffma2(ull a, ull b, ull c) {
    ull d;
    asm("fma.rn.f32x2 %0, %1, %2, %3;" : "=l"(d) : "l"(a), "l"(b), "l"(c));
    return d;
}
__device__ __forceinline__ ull pack2(float lo, float hi) {
    ull r;
    asm("mov.b64 %0, {%1, %2};" : "=l"(r) : "f"(lo), "f"(hi));
    return r;
}
__device__ __forceinline__ void unpack2(ull v, float& lo, float& hi) {
    asm("mov.b64 {%0, %1}, %2;" : "=f"(lo), "=f"(hi) : "l"(v));
}
__device__ __forceinline__ u32 smem_u32(const void* p) {
    u32 a;
    asm("{ .reg .u64 t; cvta.to.shared.u64 t, %1; cvt.u32.u64 %0, t; }" : "=r"(a) : "l"(p));
    return a;
}
__device__ __forceinline__ void cp_async4(u32 saddr, const void* gaddr) {
    asm volatile("cp.async.ca.shared.global [%0], [%1], 4;" :: "r"(saddr), "l"(gaddr));
}

static constexpr int THREADS = 384;         // 12 warps -> 3 warps/SMSP
static constexpr int R = 2;                 // rows per thread
static constexpr int TILE = THREADS * R;    // 768 rows per tile

// SMEM layout (float offsets); 16B-aligned regions.
static constexpr int W1_STRIDE = 36;        // 144B = 9 x 16B (odd) per feature row
static constexpr int W2_STRIDE = 20;        // 80B = 5 x 16B (odd)
static constexpr int OFF_XS  = 0;                          // verbatim [768][63] = 48384
static constexpr int OFF_WT1 = OFF_XS + TILE * 63;         // 48384 : 64*36 = 2304
static constexpr int OFF_WT2 = OFF_WT1 + 64 * W1_STRIDE;   // 50688 : 32*20 = 640
static constexpr int OFF_W3  = OFF_WT2 + 32 * W2_STRIDE;   // 51328 : 16
static constexpr int OFF_B1  = OFF_W3 + 16;                // 51344 : 32
static constexpr int OFF_B2  = OFF_B1 + 32;                // 51376 : 16
static constexpr int SMEM_FLOATS = OFF_B2 + 16;            // 51392
static constexpr int SMEM_BYTES  = SMEM_FLOATS * 4;        // 205568 -> 1 CTA/SM

// Stage col-block A: columns 0..31 of all `rows` rows (warp reads 128B runs).
__device__ __forceinline__ void stage_colA(u32 s_xs, const float* __restrict__ x_c,
                                           long long base, int rows, int tid)
{
    const float* src = x_c + base * 63;
    const int n = rows * 32;
    for (int e = tid; e < n; e += THREADS) {
        const int r = e >> 5;
        const int c = e & 31;
        const int off = r * 63 + c;
        cp_async4(s_xs + (u32)off * 4u, src + off);
    }
}

// Stage col-block B: columns 32..62 of all `rows` rows.
__device__ __forceinline__ void stage_colB(u32 s_xs, const float* __restrict__ x_c,
                                           long long base, int rows, int tid)
{
    const float* src = x_c + base * 63;
    const int n = rows * 31;
    for (int e = tid; e < n; e += THREADS) {
        const int r = e / 31;
        const int c = 32 + (e - r * 31);
        const int off = r * 63 + c;
        cp_async4(s_xs + (u32)off * 4u, src + off);
    }
}

__global__ void __launch_bounds__(THREADS, 1)
hybridq_kernel(const float* __restrict__ x_q,
               const float* __restrict__ x_c,
               const float* __restrict__ q_params,
               const float* __restrict__ w1,
               const float* __restrict__ b1,
               const float* __restrict__ w2,
               const float* __restrict__ b2,
               const float* __restrict__ w3,
               const float* __restrict__ b3,
               float* __restrict__ out,
               int B, int nt)
{
    extern __shared__ float sm[];
    float* XS  = sm + OFF_XS;
    float* WT1 = sm + OFF_WT1;
    float* WT2 = sm + OFF_WT2;
    float* W3S = sm + OFF_W3;
    float* B1S = sm + OFF_B1;
    float* B2S = sm + OFF_B2;

    const int tid = threadIdx.x;
    const u32 s_xs = smem_u32(XS);

    // ---- prologue: stage first tile as two committed col-block groups ----
    int t = blockIdx.x;
    {
        const int rows = min(TILE, B - t * TILE);
        stage_colA(s_xs, x_c, (long long)t * TILE, rows, tid);
        asm volatile("cp.async.commit_group;");
        stage_colB(s_xs, x_c, (long long)t * TILE, rows, tid);
        asm volatile("cp.async.commit_group;");
    }

    // ---- stage weights while the first tile flies ----
    #pragma unroll
    for (int i = 0; i < 6; ++i) {
        int idx = tid + THREADS * i;            // w1 is [32][64]
        if (idx < 2048) {
            int tt = idx >> 6, k = idx & 63;
            WT1[k * W1_STRIDE + tt] = w1[idx];
        }
    }
    #pragma unroll
    for (int i = 0; i < 2; ++i) {
        int idx = tid + THREADS * i;            // w2 is [16][32]
        if (idx < 512) {
            int m = idx >> 5, j = idx & 31;
            WT2[j * W2_STRIDE + m] = w2[idx];
        }
    }
    if (tid < 16) W3S[tid] = w3[tid];
    if (tid < 32) B1S[tid] = b1[tid];
    if (tid < 16) B2S[tid] = b2[tid];

    const float qp1 = __ldg(q_params + 1);
    const float qp2 = __ldg(q_params + 2);
    const float b3v = __ldg(b3);

    const int xb0 = tid * 63;
    const int xb1 = (tid + THREADS) * 63;

    for (; t < nt; t += gridDim.x) {
        const long long base = (long long)t * TILE;
        const int row0 = (int)base + tid;
        const int row1 = row0 + THREADS;
        const int tn = t + gridDim.x;
        const int nrows = (tn < nt) ? min(TILE, B - tn * TILE) : 0;

        // q-feature operand prefetch (independent LDGs, fire early)
        float q0x1 = 0.0f, q0x2 = 0.0f, q1x1 = 0.0f, q1x2 = 0.0f;
        if (row0 < B) {
            q0x1 = __ldg(x_q + (long long)row0 * 3 + 1);
            q0x2 = __ldg(x_q + (long long)row0 * 3 + 2);
        }
        if (row1 < B) {
            q1x1 = __ldg(x_q + (long long)row1 * 3 + 1);
            q1x2 = __ldg(x_q + (long long)row1 * 3 + 2);
        }

        // ===== phase A: col-block A resident (B-block may still fly) =====
        asm volatile("cp.async.wait_group 1;");
        __syncthreads();

        ull acc[R][16];
        #pragma unroll
        for (int p = 0; p < 16; ++p) {
            const ull bp = *reinterpret_cast<const ull*>(B1S + 2 * p);
            acc[0][p] = bp; acc[1][p] = bp;
        }

        // feature 0 : q_out (closed-form circuit)
        {
            const float q0 = __cosf(q0x1 + qp1) * __cosf(q0x2 + qp2);
            const float q1 = __cosf(q1x1 + qp1) * __cosf(q1x2 + qp2);
            const ull xx0 = pack2(q0, q0);
            const ull xx1 = pack2(q1, q1);
            #pragma unroll
            for (int qd = 0; qd < 8; ++qd) {
                const ulonglong2 wv = *reinterpret_cast<const ulonglong2*>(WT1 + 4 * qd);
                acc[0][2 * qd]     = ffma2(wv.x, xx0, acc[0][2 * qd]);
                acc[1][2 * qd]     = ffma2(wv.x, xx1, acc[1][2 * qd]);
                acc[0][2 * qd + 1] = ffma2(wv.y, xx0, acc[0][2 * qd + 1]);
                acc[1][2 * qd + 1] = ffma2(wv.y, xx1, acc[1][2 * qd + 1]);
            }
        }

        // features 1..32 : x_c cols 0..31, both rows in the same loop
        #pragma unroll 8
        for (int k = 1; k <= 32; ++k) {
            const float x0 = XS[xb0 + (k - 1)];
            const float x1 = XS[xb1 + (k - 1)];
            const ull xx0 = pack2(x0, x0);
            const ull xx1 = pack2(x1, x1);
            const float* wf = WT1 + k * W1_STRIDE;
            #pragma unroll
            for (int qd = 0; qd < 8; ++qd) {
                const ulonglong2 wv = *reinterpret_cast<const ulonglong2*>(wf + 4 * qd);
                acc[0][2 * qd]     = ffma2(wv.x, xx0, acc[0][2 * qd]);
                acc[1][2 * qd]     = ffma2(wv.x, xx1, acc[1][2 * qd]);
                acc[0][2 * qd + 1] = ffma2(wv.y, xx0, acc[0][2 * qd + 1]);
                acc[1][2 * qd + 1] = ffma2(wv.y, xx1, acc[1][2 * qd + 1]);
            }
        }

        // col-block A of this tile is dead -> restage it for the next tile
        __syncthreads();
        if (tn < nt)
            stage_colA(s_xs, x_c, (long long)tn * TILE, nrows, tid);
        asm volatile("cp.async.commit_group;");

        // ===== phase B: col-block B resident (next A-block may still fly) =====
        asm volatile("cp.async.wait_group 1;");
        __syncthreads();

        // features 33..63 : x_c cols 32..62
        #pragma unroll 8
        for (int k = 33; k < 64; ++k) {
            const float x0 = XS[xb0 + (k - 1)];
            const float x1 = XS[xb1 + (k - 1)];
            const ull xx0 = pack2(x0, x0);
            const ull xx1 = pack2(x1, x1);
            const float* wf = WT1 + k * W1_STRIDE;
            #pragma unroll
            for (int qd = 0; qd < 8; ++qd) {
                const ulonglong2 wv = *reinterpret_cast<const ulonglong2*>(wf + 4 * qd);
                acc[0][2 * qd]     = ffma2(wv.x, xx0, acc[0][2 * qd]);
                acc[1][2 * qd]     = ffma2(wv.x, xx1, acc[1][2 * qd]);
                acc[0][2 * qd + 1] = ffma2(wv.y, xx0, acc[0][2 * qd + 1]);
                acc[1][2 * qd + 1] = ffma2(wv.y, xx1, acc[1][2 * qd + 1]);
            }
        }

        // col-block B dead -> restage for next tile
        __syncthreads();
        if (tn < nt)
            stage_colB(s_xs, x_c, (long long)tn * TILE, nrows, tid);
        asm volatile("cp.async.commit_group;");

        // ---- relu -> h1 ----
        float h1[R][32];
        #pragma unroll
        for (int r = 0; r < R; ++r)
            #pragma unroll
            for (int p = 0; p < 16; ++p) {
                float lo, hi;
                unpack2(acc[r][p], lo, hi);
                h1[r][2 * p]     = fmaxf(lo, 0.0f);
                h1[r][2 * p + 1] = fmaxf(hi, 0.0f);
            }

        // ============ layer 2: h2[16] = relu(W2 @ h1 + b2) ============
        ull a2[R][8];
        #pragma unroll
        for (int p = 0; p < 8; ++p) {
            const ull bp = *reinterpret_cast<const ull*>(B2S + 2 * p);
            a2[0][p] = bp; a2[1][p] = bp;
        }
        #pragma unroll
        for (int j = 0; j < 32; ++j) {
            const float* w2r = WT2 + j * W2_STRIDE;
            const ull xx0 = pack2(h1[0][j], h1[0][j]);
            const ull xx1 = pack2(h1[1][j], h1[1][j]);
            #pragma unroll
            for (int v = 0; v < 4; ++v) {
                const ulonglong2 wv = *reinterpret_cast<const ulonglong2*>(w2r + 4 * v);
                a2[0][2 * v]     = ffma2(wv.x, xx0, a2[0][2 * v]);
                a2[1][2 * v]     = ffma2(wv.x, xx1, a2[1][2 * v]);
                a2[0][2 * v + 1] = ffma2(wv.y, xx0, a2[0][2 * v + 1]);
                a2[1][2 * v + 1] = ffma2(wv.y, xx1, a2[1][2 * v + 1]);
            }
        }

        float h2[R][16];
        #pragma unroll
        for (int r = 0; r < R; ++r)
            #pragma unroll
            for (int p = 0; p < 8; ++p) {
                float lo, hi;
                unpack2(a2[r][p], lo, hi);
                h2[r][2 * p]     = fmaxf(lo, 0.0f);
                h2[r][2 * p + 1] = fmaxf(hi, 0.0f);
            }

        // ============ layer 3: out = w3 . h2 + b3 ============
        #pragma unroll
        for (int r = 0; r < R; ++r) {
            ull a3 = pack2(b3v, 0.0f);
            #pragma unroll
            for (int v = 0; v < 4; ++v) {
                const ulonglong2 wv = *reinterpret_cast<const ulonglong2*>(W3S + 4 * v);
                a3 = ffma2(wv.x, pack2(h2[r][4 * v],     h2[r][4 * v + 1]), a3);
                a3 = ffma2(wv.y, pack2(h2[r][4 * v + 2], h2[r][4 * v + 3]), a3);
            }
            float lo, hi;
            unpack2(a3, lo, hi);
            const int row = row0 + r * THREADS;
            if (row < B) out[row] = lo + hi;
        }
    }
}

extern "C" void kernel_launch(void* const* d_in, const int* in_sizes, int n_in,
                              void* d_out, int out_size)
{
    const float* x_q      = (const float*)d_in[0];
    const float* x_c      = (const float*)d_in[1];
    const float* q_params = (const float*)d_in[2];
    const float* w1       = (const float*)d_in[3];
    const float* b1       = (const float*)d_in[4];
    const float* w2       = (const float*)d_in[5];
    const float* b2       = (const float*)d_in[6];
    const float* w3       = (const float*)d_in[7];
    const float* b3       = (const float*)d_in[8];
    float* out            = (float*)d_out;

    const int B = in_sizes[0] / 3;
    const int nt = (B + TILE - 1) / TILE;

    int dev = 0, sms = 148;
    cudaGetDevice(&dev);
    cudaDeviceGetAttribute(&sms, cudaDevAttrMultiProcessorCount, dev);
    int blocks = sms < nt ? sms : nt;

    cudaFuncSetAttribute(hybridq_kernel,
                         cudaFuncAttributeMaxDynamicSharedMemorySize, SMEM_BYTES);

    hybridq_kernel<<<blocks, THREADS, SMEM_BYTES>>>(
        x_q, x_c, q_params, w1, b1, w2, b2, w3, b3, out, B, nt);
}

// round 13
// speedup vs baseline: 1.3286x; 1.3286x over previous
#include <cuda_runtime.h>

typedef unsigned long long ull;
typedef unsigned int u32;

// ---- f32x2 packed helpers (Blackwell) ----
__device__ __forceinline__ ull ffma2(ull a, ull b, ull c) {
    ull d;
    asm("fma.rn.f32x2 %0, %1, %2, %3;" : "=l"(d) : "l"(a), "l"(b), "l"(c));
    return d;
}
__device__ __forceinline__ ull pack2(float lo, float hi) {
    ull r;
    asm("mov.b64 %0, {%1, %2};" : "=l"(r) : "f"(lo), "f"(hi));
    return r;
}
__device__ __forceinline__ void unpack2(ull v, float& lo, float& hi) {
    asm("mov.b64 {%0, %1}, %2;" : "=f"(lo), "=f"(hi) : "l"(v));
}
__device__ __forceinline__ u32 smem_u32(const void* p) {
    u32 a;
    asm("{ .reg .u64 t; cvta.to.shared.u64 t, %1; cvt.u32.u64 %0, t; }" : "=r"(a) : "l"(p));
    return a;
}
__device__ __forceinline__ void cp_async16(u32 saddr, const void* gaddr) {
    asm volatile("cp.async.cg.shared.global [%0], [%1], 16;" :: "r"(saddr), "l"(gaddr));
}

static constexpr int THREADS = 192;         // 6 warps/CTA; 2 CTAs/SM -> 3 warps/SMSP
static constexpr int R = 2;                 // rows per thread
static constexpr int TILE = THREADS * R;    // 384 rows per tile

// SMEM layout (float offsets); 16B-aligned regions.
static constexpr int W1_STRIDE = 36;        // 144B = 9 x 16B (odd) per feature row
static constexpr int W2_STRIDE = 20;        // 80B = 5 x 16B (odd)
static constexpr int OFF_XS  = 0;                          // verbatim [384][63] = 24192
static constexpr int OFF_WT1 = OFF_XS + TILE * 63;         // 24192 : 64*36 = 2304
static constexpr int OFF_WT2 = OFF_WT1 + 64 * W1_STRIDE;   // 26496 : 32*20 = 640
static constexpr int OFF_W3  = OFF_WT2 + 32 * W2_STRIDE;   // 27136 : 16
static constexpr int OFF_B1  = OFF_W3 + 16;                // 27152 : 32
static constexpr int OFF_B2  = OFF_B1 + 32;                // 27184 : 16
static constexpr int SMEM_FLOATS = OFF_B2 + 16;            // 27200
static constexpr int SMEM_BYTES  = SMEM_FLOATS * 4;        // 108800 -> 2 CTAs/SM

__device__ __forceinline__ void stage_tile(u32 s_xs, const float* __restrict__ x_c,
                                           long long base, int rows, int tid)
{
    // rows*63 divisible by 4 for rows%4==0 (TILE=384 and the 256-row last tile).
    const float* src = x_c + base * 63;
    const int chunks = (rows * 63) >> 2;
    for (int i = tid; i < chunks; i += THREADS)
        cp_async16(s_xs + (u32)i * 16u, src + 4 * i);
}

__global__ void __launch_bounds__(THREADS, 2)
hybridq_kernel(const float* __restrict__ x_q,
               const float* __restrict__ x_c,
               const float* __restrict__ q_params,
               const float* __restrict__ w1,
               const float* __restrict__ b1,
               const float* __restrict__ w2,
               const float* __restrict__ b2,
               const float* __restrict__ w3,
               const float* __restrict__ b3,
               float* __restrict__ out,
               int B, int nt)
{
    extern __shared__ float sm[];
    float* XS  = sm + OFF_XS;
    float* WT1 = sm + OFF_WT1;
    float* WT2 = sm + OFF_WT2;
    float* W3S = sm + OFF_W3;
    float* B1S = sm + OFF_B1;
    float* B2S = sm + OFF_B2;

    const int tid = threadIdx.x;
    const u32 s_xs = smem_u32(XS);

    // ---- stage first tile (async, fire-and-forget) ----
    int t = blockIdx.x;
    if (t < nt) {
        int rows = min(TILE, B - t * TILE);
        stage_tile(s_xs, x_c, (long long)t * TILE, rows, tid);
    }
    asm volatile("cp.async.commit_group;");

    // ---- stage weights while first tile flies ----
    #pragma unroll
    for (int i = 0; i < 11; ++i) {
        int idx = tid + THREADS * i;            // w1 is [32][64], 2048 elems
        if (idx < 2048) {
            int tt = idx >> 6, k = idx & 63;
            WT1[k * W1_STRIDE + tt] = w1[idx];
        }
    }
    #pragma unroll
    for (int i = 0; i < 3; ++i) {
        int idx = tid + THREADS * i;            // w2 is [16][32], 512 elems
        if (idx < 512) {
            int m = idx >> 5, j = idx & 31;
            WT2[j * W2_STRIDE + m] = w2[idx];
        }
    }
    if (tid < 16) W3S[tid] = w3[tid];
    if (tid < 32) B1S[tid] = b1[tid];
    if (tid < 16) B2S[tid] = b2[tid];

    const float qp1 = __ldg(q_params + 1);
    const float qp2 = __ldg(q_params + 2);
    const float b3v = __ldg(b3);

    const int xb0 = tid * 63;
    const int xb1 = (tid + THREADS) * 63;

    for (; t < nt; t += gridDim.x) {
        const long long base = (long long)t * TILE;
        const int row0 = (int)base + tid;
        const int row1 = row0 + THREADS;

        // prefetch q-feature operands early (independent of the barrier)
        float q0x1 = 0.0f, q0x2 = 0.0f, q1x1 = 0.0f, q1x2 = 0.0f;
        if (row0 < B) {
            q0x1 = __ldg(x_q + (long long)row0 * 3 + 1);
            q0x2 = __ldg(x_q + (long long)row0 * 3 + 2);
        }
        if (row1 < B) {
            q1x1 = __ldg(x_q + (long long)row1 * 3 + 1);
            q1x2 = __ldg(x_q + (long long)row1 * 3 + 2);
        }

        // current tile must be resident
        asm volatile("cp.async.wait_group 0;");
        __syncthreads();

        // ============ layer 1: h1[32] = relu(W1 @ [q,x] + b1) ============
        ull acc[R][16];
        #pragma unroll
        for (int p = 0; p < 16; ++p) {
            const ull bp = *reinterpret_cast<const ull*>(B1S + 2 * p);
            acc[0][p] = bp; acc[1][p] = bp;
        }

        // feature 0 : q_out (closed-form circuit)
        {
            const float q0 = __cosf(q0x1 + qp1) * __cosf(q0x2 + qp2);
            const float q1 = __cosf(q1x1 + qp1) * __cosf(q1x2 + qp2);
            const ull xx0 = pack2(q0, q0);
            const ull xx1 = pack2(q1, q1);
            #pragma unroll
            for (int qd = 0; qd < 8; ++qd) {
                const ulonglong2 wv = *reinterpret_cast<const ulonglong2*>(WT1 + 4 * qd);
                acc[0][2 * qd]     = ffma2(wv.x, xx0, acc[0][2 * qd]);
                acc[1][2 * qd]     = ffma2(wv.x, xx1, acc[1][2 * qd]);
                acc[0][2 * qd + 1] = ffma2(wv.y, xx0, acc[0][2 * qd + 1]);
                acc[1][2 * qd + 1] = ffma2(wv.y, xx1, acc[1][2 * qd + 1]);
            }
        }

        // features 1..63 (stride-63 rows -> conflict-free LDS.32)
        #pragma unroll 9
        for (int k = 0; k < 63; ++k) {
            const float x0 = XS[xb0 + k];
            const float x1 = XS[xb1 + k];
            const ull xx0 = pack2(x0, x0);
            const ull xx1 = pack2(x1, x1);
            const float* wf = WT1 + (k + 1) * W1_STRIDE;
            #pragma unroll
            for (int qd = 0; qd < 8; ++qd) {
                const ulonglong2 wv = *reinterpret_cast<const ulonglong2*>(wf + 4 * qd);
                acc[0][2 * qd]     = ffma2(wv.x, xx0, acc[0][2 * qd]);
                acc[1][2 * qd]     = ffma2(wv.x, xx1, acc[1][2 * qd]);
                acc[0][2 * qd + 1] = ffma2(wv.y, xx0, acc[0][2 * qd + 1]);
                acc[1][2 * qd + 1] = ffma2(wv.y, xx1, acc[1][2 * qd + 1]);
            }
        }

        // XS is now dead for this tile: restage next tile under layers 2/3
        __syncthreads();
        {
            const int tn = t + gridDim.x;
            if (tn < nt) {
                int nrows = min(TILE, B - tn * TILE);
                stage_tile(s_xs, x_c, (long long)tn * TILE, nrows, tid);
            }
            asm volatile("cp.async.commit_group;");
        }

        // relu -> h1
        float h1[R][32];
        #pragma unroll
        for (int r = 0; r < R; ++r)
            #pragma unroll
            for (int p = 0; p < 16; ++p) {
                float lo, hi;
                unpack2(acc[r][p], lo, hi);
                h1[r][2 * p]     = fmaxf(lo, 0.0f);
                h1[r][2 * p + 1] = fmaxf(hi, 0.0f);
            }

        // ============ layer 2: h2[16] = relu(W2 @ h1 + b2) ============
        ull a2[R][8];
        #pragma unroll
        for (int p = 0; p < 8; ++p) {
            const ull bp = *reinterpret_cast<const ull*>(B2S + 2 * p);
            a2[0][p] = bp; a2[1][p] = bp;
        }
        #pragma unroll
        for (int j = 0; j < 32; ++j) {
            const float* w2r = WT2 + j * W2_STRIDE;
            const ull xx0 = pack2(h1[0][j], h1[0][j]);
            const ull xx1 = pack2(h1[1][j], h1[1][j]);
            #pragma unroll
            for (int v = 0; v < 4; ++v) {
                const ulonglong2 wv = *reinterpret_cast<const ulonglong2*>(w2r + 4 * v);
                a2[0][2 * v]     = ffma2(wv.x, xx0, a2[0][2 * v]);
                a2[1][2 * v]     = ffma2(wv.x, xx1, a2[1][2 * v]);
                a2[0][2 * v + 1] = ffma2(wv.y, xx0, a2[0][2 * v + 1]);
                a2[1][2 * v + 1] = ffma2(wv.y, xx1, a2[1][2 * v + 1]);
            }
        }

        float h2[R][16];
        #pragma unroll
        for (int r = 0; r < R; ++r)
            #pragma unroll
            for (int p = 0; p < 8; ++p) {
                float lo, hi;
                unpack2(a2[r][p], lo, hi);
                h2[r][2 * p]     = fmaxf(lo, 0.0f);
                h2[r][2 * p + 1] = fmaxf(hi, 0.0f);
            }

        // ============ layer 3: out = w3 . h2 + b3 ============
        #pragma unroll
        for (int r = 0; r < R; ++r) {
            ull a3 = pack2(b3v, 0.0f);
            #pragma unroll
            for (int v = 0; v < 4; ++v) {
                const ulonglong2 wv = *reinterpret_cast<const ulonglong2*>(W3S + 4 * v);
                a3 = ffma2(wv.x, pack2(h2[r][4 * v],     h2[r][4 * v + 1]), a3);
                a3 = ffma2(wv.y, pack2(h2[r][4 * v + 2], h2[r][4 * v + 3]), a3);
            }
            float lo, hi;
            unpack2(a3, lo, hi);
            const int row = row0 + r * THREADS;
            if (row < B) out[row] = lo + hi;
        }
    }
}

extern "C" void kernel_launch(void* const* d_in, const int* in_sizes, int n_in,
                              void* d_out, int out_size)
{
    const float* x_q      = (const float*)d_in[0];
    const float* x_c      = (const float*)d_in[1];
    const float* q_params = (const float*)d_in[2];
    const float* w1       = (const float*)d_in[3];
    const float* b1       = (const float*)d_in[4];
    const float* w2       = (const float*)d_in[5];
    const float* b2       = (const float*)d_in[6];
    const float* w3       = (const float*)d_in[7];
    const float* b3       = (const float*)d_in[8];
    float* out            = (float*)d_out;

    const int B = in_sizes[0] / 3;
    const int nt = (B + TILE - 1) / TILE;

    int dev = 0, sms = 148;
    cudaGetDevice(&dev);
    cudaDeviceGetAttribute(&sms, cudaDevAttrMultiProcessorCount, dev);
    int blocks = 2 * sms;                 // 2 CTAs per SM
    if (blocks > nt) blocks = nt;

    cudaFuncSetAttribute(hybridq_kernel,
                         cudaFuncAttributeMaxDynamicSharedMemorySize, SMEM_BYTES);

    hybridq_kernel<<<blocks, THREADS, SMEM_BYTES>>>(
        x_q, x_c, q_params, w1, b1, w2, b2, w3, b3, out, B, nt);
}

// round 14
// speedup vs baseline: 1.4739x; 1.1094x over previous
#include <cuda_runtime.h>

typedef unsigned long long ull;
typedef unsigned int u32;

// ---- f32x2 packed helpers (Blackwell) ----
__device__ __forceinline__ ull ffma2(ull a, ull b, ull c) {
    ull d;
    asm("fma.rn.f32x2 %0, %1, %2, %3;" : "=l"(d) : "l"(a), "l"(b), "l"(c));
    return d;
}
__device__ __forceinline__ ull pack2(float lo, float hi) {
    ull r;
    asm("mov.b64 %0, {%1, %2};" : "=l"(r) : "f"(lo), "f"(hi));
    return r;
}
__device__ __forceinline__ void unpack2(ull v, float& lo, float& hi) {
    asm("mov.b64 {%0, %1}, %2;" : "=f"(lo), "=f"(hi) : "l"(v));
}
__device__ __forceinline__ u32 smem_u32(const void* p) {
    u32 a;
    asm("{ .reg .u64 t; cvta.to.shared.u64 t, %1; cvt.u32.u64 %0, t; }" : "=r"(a) : "l"(p));
    return a;
}
__device__ __forceinline__ void cp_async16(u32 saddr, const void* gaddr) {
    asm volatile("cp.async.cg.shared.global [%0], [%1], 16;" :: "r"(saddr), "l"(gaddr));
}
__device__ __forceinline__ void l2_prefetch_bulk(const void* gaddr, u32 bytes) {
    asm volatile("cp.async.bulk.prefetch.L2.global [%0], %1;" :: "l"(gaddr), "r"(bytes));
}

static constexpr int THREADS = 384;         // 12 warps -> 3 warps/SMSP
static constexpr int R = 2;                 // rows per thread
static constexpr int TILE = THREADS * R;    // 768 rows per tile

// SMEM layout (float offsets); 16B-aligned regions.
static constexpr int W1_STRIDE = 36;        // 144B = 9 x 16B (odd) per feature row
static constexpr int W2_STRIDE = 20;        // 80B = 5 x 16B (odd)
static constexpr int OFF_XS  = 0;                          // verbatim [768][63] = 48384
static constexpr int OFF_WT1 = OFF_XS + TILE * 63;         // 48384 : 64*36 = 2304
static constexpr int OFF_WT2 = OFF_WT1 + 64 * W1_STRIDE;   // 50688 : 32*20 = 640
static constexpr int OFF_W3  = OFF_WT2 + 32 * W2_STRIDE;   // 51328 : 16
static constexpr int OFF_B1  = OFF_W3 + 16;                // 51344 : 32
static constexpr int OFF_B2  = OFF_B1 + 32;                // 51376 : 16
static constexpr int SMEM_FLOATS = OFF_B2 + 16;            // 51392
static constexpr int SMEM_BYTES  = SMEM_FLOATS * 4;        // 205568 -> 1 CTA/SM

__device__ __forceinline__ void stage_tile(u32 s_xs, const float* __restrict__ x_c,
                                           long long base, int rows, int tid)
{
    const float* src = x_c + base * 63;
    const int chunks = (rows * 63) >> 2;   // rows%4==0 for all tiles of this B
    for (int i = tid; i < chunks; i += THREADS)
        cp_async16(s_xs + (u32)i * 16u, src + 4 * i);
}

__global__ void __launch_bounds__(THREADS, 1)
hybridq_kernel(const float* __restrict__ x_q,
               const float* __restrict__ x_c,
               const float* __restrict__ q_params,
               const float* __restrict__ w1,
               const float* __restrict__ b1,
               const float* __restrict__ w2,
               const float* __restrict__ b2,
               const float* __restrict__ w3,
               const float* __restrict__ b3,
               float* __restrict__ out,
               int B, int nt)
{
    extern __shared__ float sm[];
    float* XS  = sm + OFF_XS;
    float* WT1 = sm + OFF_WT1;
    float* WT2 = sm + OFF_WT2;
    float* W3S = sm + OFF_W3;
    float* B1S = sm + OFF_B1;
    float* B2S = sm + OFF_B2;

    const int tid = threadIdx.x;
    const u32 s_xs = smem_u32(XS);

    // ---- stage first tile (async, fire-and-forget) ----
    int t = blockIdx.x;
    if (t < nt) {
        int rows = min(TILE, B - t * TILE);
        stage_tile(s_xs, x_c, (long long)t * TILE, rows, tid);
    }
    asm volatile("cp.async.commit_group;");

    // ---- stage weights while first tile flies ----
    #pragma unroll
    for (int i = 0; i < 6; ++i) {
        int idx = tid + THREADS * i;            // w1 is [32][64]
        if (idx < 2048) {
            int tt = idx >> 6, k = idx & 63;
            WT1[k * W1_STRIDE + tt] = w1[idx];
        }
    }
    #pragma unroll
    for (int i = 0; i < 2; ++i) {
        int idx = tid + THREADS * i;            // w2 is [16][32]
        if (idx < 512) {
            int m = idx >> 5, j = idx & 31;
            WT2[j * W2_STRIDE + m] = w2[idx];
        }
    }
    if (tid < 16) W3S[tid] = w3[tid];
    if (tid < 32) B1S[tid] = b1[tid];
    if (tid < 16) B2S[tid] = b2[tid];

    const float qp1 = __ldg(q_params + 1);
    const float qp2 = __ldg(q_params + 2);
    const float b3v = __ldg(b3);

    const int xb0 = tid * 63;
    const int xb1 = (tid + THREADS) * 63;

    for (; t < nt; t += gridDim.x) {
        const long long base = (long long)t * TILE;
        const int row0 = (int)base + tid;
        const int row1 = row0 + THREADS;
        const int tn = t + gridDim.x;

        // prefetch q-feature operands early (independent of the barrier)
        float q0x1 = 0.0f, q0x2 = 0.0f, q1x1 = 0.0f, q1x2 = 0.0f;
        if (row0 < B) {
            q0x1 = __ldg(x_q + (long long)row0 * 3 + 1);
            q0x2 = __ldg(x_q + (long long)row0 * 3 + 2);
        }
        if (row1 < B) {
            q1x1 = __ldg(x_q + (long long)row1 * 3 + 1);
            q1x2 = __ldg(x_q + (long long)row1 * 3 + 2);
        }

        // current tile must be resident
        asm volatile("cp.async.wait_group 0;");
        __syncthreads();

        // ---- warm L2 with the NEXT tile while layer 1 computes (pure hint) ----
        if (tid == 0 && tn < nt) {
            const int nrows = min(TILE, B - tn * TILE);
            l2_prefetch_bulk(x_c + (long long)tn * TILE * 63,
                             (u32)(nrows * 63) * 4u);
        }

        // ============ layer 1: h1[32] = relu(W1 @ [q,x] + b1) ============
        ull acc[R][16];
        #pragma unroll
        for (int p = 0; p < 16; ++p) {
            const ull bp = *reinterpret_cast<const ull*>(B1S + 2 * p);
            acc[0][p] = bp; acc[1][p] = bp;
        }

        // feature 0 : q_out (closed-form circuit)
        {
            const float q0 = __cosf(q0x1 + qp1) * __cosf(q0x2 + qp2);
            const float q1 = __cosf(q1x1 + qp1) * __cosf(q1x2 + qp2);
            const ull xx0 = pack2(q0, q0);
            const ull xx1 = pack2(q1, q1);
            #pragma unroll
            for (int qd = 0; qd < 8; ++qd) {
                const ulonglong2 wv = *reinterpret_cast<const ulonglong2*>(WT1 + 4 * qd);
                acc[0][2 * qd]     = ffma2(wv.x, xx0, acc[0][2 * qd]);
                acc[1][2 * qd]     = ffma2(wv.x, xx1, acc[1][2 * qd]);
                acc[0][2 * qd + 1] = ffma2(wv.y, xx0, acc[0][2 * qd + 1]);
                acc[1][2 * qd + 1] = ffma2(wv.y, xx1, acc[1][2 * qd + 1]);
            }
        }

        // features 1..63 (stride-63 rows -> conflict-free LDS.32)
        #pragma unroll 9
        for (int k = 0; k < 63; ++k) {
            const float x0 = XS[xb0 + k];
            const float x1 = XS[xb1 + k];
            const ull xx0 = pack2(x0, x0);
            const ull xx1 = pack2(x1, x1);
            const float* wf = WT1 + (k + 1) * W1_STRIDE;
            #pragma unroll
            for (int qd = 0; qd < 8; ++qd) {
                const ulonglong2 wv = *reinterpret_cast<const ulonglong2*>(wf + 4 * qd);
                acc[0][2 * qd]     = ffma2(wv.x, xx0, acc[0][2 * qd]);
                acc[1][2 * qd]     = ffma2(wv.x, xx1, acc[1][2 * qd]);
                acc[0][2 * qd + 1] = ffma2(wv.y, xx0, acc[0][2 * qd + 1]);
                acc[1][2 * qd + 1] = ffma2(wv.y, xx1, acc[1][2 * qd + 1]);
            }
        }

        // XS is now dead for this tile: restage next tile (L2-warm) under layers 2/3
        __syncthreads();
        {
            if (tn < nt) {
                int nrows = min(TILE, B - tn * TILE);
                stage_tile(s_xs, x_c, (long long)tn * TILE, nrows, tid);
            }
            asm volatile("cp.async.commit_group;");
        }

        // relu -> h1
        float h1[R][32];
        #pragma unroll
        for (int r = 0; r < R; ++r)
            #pragma unroll
            for (int p = 0; p < 16; ++p) {
                float lo, hi;
                unpack2(acc[r][p], lo, hi);
                h1[r][2 * p]     = fmaxf(lo, 0.0f);
                h1[r][2 * p + 1] = fmaxf(hi, 0.0f);
            }

        // ============ layer 2: h2[16] = relu(W2 @ h1 + b2) ============
        ull a2[R][8];
        #pragma unroll
        for (int p = 0; p < 8; ++p) {
            const ull bp = *reinterpret_cast<const ull*>(B2S + 2 * p);
            a2[0][p] = bp; a2[1][p] = bp;
        }
        #pragma unroll
        for (int j = 0; j < 32; ++j) {
            const float* w2r = WT2 + j * W2_STRIDE;
            const ull xx0 = pack2(h1[0][j], h1[0][j]);
            const ull xx1 = pack2(h1[1][j], h1[1][j]);
            #pragma unroll
            for (int v = 0; v < 4; ++v) {
                const ulonglong2 wv = *reinterpret_cast<const ulonglong2*>(w2r + 4 * v);
                a2[0][2 * v]     = ffma2(wv.x, xx0, a2[0][2 * v]);
                a2[1][2 * v]     = ffma2(wv.x, xx1, a2[1][2 * v]);
                a2[0][2 * v + 1] = ffma2(wv.y, xx0, a2[0][2 * v + 1]);
                a2[1][2 * v + 1] = ffma2(wv.y, xx1, a2[1][2 * v + 1]);
            }
        }

        float h2[R][16];
        #pragma unroll
        for (int r = 0; r < R; ++r)
            #pragma unroll
            for (int p = 0; p < 8; ++p) {
                float lo, hi;
                unpack2(a2[r][p], lo, hi);
                h2[r][2 * p]     = fmaxf(lo, 0.0f);
                h2[r][2 * p + 1] = fmaxf(hi, 0.0f);
            }

        // ============ layer 3: out = w3 . h2 + b3 ============
        #pragma unroll
        for (int r = 0; r < R; ++r) {
            ull a3 = pack2(b3v, 0.0f);
            #pragma unroll
            for (int v = 0; v < 4; ++v) {
                const ulonglong2 wv = *reinterpret_cast<const ulonglong2*>(W3S + 4 * v);
                a3 = ffma2(wv.x, pack2(h2[r][4 * v],     h2[r][4 * v + 1]), a3);
                a3 = ffma2(wv.y, pack2(h2[r][4 * v + 2], h2[r][4 * v + 3]), a3);
            }
            float lo, hi;
            unpack2(a3, lo, hi);
            const int row = row0 + r * THREADS;
            if (row < B) out[row] = lo + hi;
        }
    }
}

extern "C" void kernel_launch(void* const* d_in, const int* in_sizes, int n_in,
                              void* d_out, int out_size)
{
    const float* x_q      = (const float*)d_in[0];
    const float* x_c      = (const float*)d_in[1];
    const float* q_params = (const float*)d_in[2];
    const float* w1       = (const float*)d_in[3];
    const float* b1       = (const float*)d_in[4];
    const float* w2       = (const float*)d_in[5];
    const float* b2       = (const float*)d_in[6];
    const float* w3       = (const float*)d_in[7];
    const float* b3       = (const float*)d_in[8];
    float* out            = (float*)d_out;

    const int B = in_sizes[0] / 3;
    const int nt = (B + TILE - 1) / TILE;

    int dev = 0, sms = 148;
    cudaGetDevice(&dev);
    cudaDeviceGetAttribute(&sms, cudaDevAttrMultiProcessorCount, dev);
    int blocks = sms < nt ? sms : nt;

    cudaFuncSetAttribute(hybridq_kernel,
                         cudaFuncAttributeMaxDynamicSharedMemorySize, SMEM_BYTES);

    hybridq_kernel<<<blocks, THREADS, SMEM_BYTES>>>(
        x_q, x_c, q_params, w1, b1, w2, b2, w3, b3, out, B, nt);
}